// round 13
// baseline (speedup 1.0000x reference)
#include <cuda_runtime.h>
#include <cuda_bf16.h>

#define TPB   256
#define NB    32           // batch
#define BPB   8            // batches per block
#define NBG   (NB / BPB)   // batch groups (grid.y)
#define NG    20           // GT boxes per image
#define NLVL  5

struct LvlInfo {
    int aoff[NLVL + 1];
    int boff[NLVL + 1];
};

// Packed (iou_bits << 32) | (0xFFFFFFFF - local_anchor_idx) per (b,lvl,g).
// IoU >= 0 => float bits order as uints; inverted idx => atomicMax ties to the
// SMALLEST anchor index (jnp.argmax first-wins). Zero at load; last block
// re-zeroes after consuming, so graph replays start clean.
__device__ unsigned long long g_gtpack[NB * NLVL * NG];
__device__ int g_done;

// Correctly-rounded fp32 division, branch-free (Markstein fast path).
// Bit-identical to IEEE div.rn.f32 for the operands seen here.
__device__ __forceinline__ float div_rn_fast(float n, float d) {
    float r;
    asm("rcp.approx.ftz.f32 %0, %1;" : "=f"(r) : "f"(d));
    float e  = __fmaf_rn(-d, r, 1.0f);
    r        = __fmaf_rn(e, r, r);
    float q  = __fmul_rn(n, r);
    float e2 = __fmaf_rn(-d, q, n);
    return __fmaf_rn(e2, r, q);
}

__device__ __forceinline__ const float* sel_anchor(int l,
    const float* a0, const float* a1, const float* a2, const float* a3, const float* a4) {
    switch (l) {
        case 0: return a0;
        case 1: return a1;
        case 2: return a2;
        case 3: return a3;
        default: return a4;
    }
}

__global__ __launch_bounds__(TPB) void main_kernel(
    const float* __restrict__ bb,   // (B, G, 4)
    const int*   __restrict__ ids,  // (B, G)
    const float* __restrict__ a0, const float* __restrict__ a1,
    const float* __restrict__ a2, const float* __restrict__ a3,
    const float* __restrict__ a4,
    float* __restrict__ out, LvlInfo L)
{
    __shared__ float4 sbox[BPB][NG];
    __shared__ float  sarea[BPB][NG], sid[BPB][NG];
    __shared__ int    s_last;
    // Fixup staging (used only by the last block; ~15.4 KB).
    __shared__ int    s_ag[NB * NG];
    __shared__ float  s_lab[NB * NG];
    __shared__ __align__(16) float4 s_reg[NB * NG];

    const int tid  = threadIdx.x;
    const int lane = tid & 31;
    const int b0   = blockIdx.y * BPB;

    // Load GT data for all BPB batches (160 threads, one GT each).
    if (tid < BPB * NG) {
        const int i = tid / NG, g = tid % NG;
        float4 g4 = reinterpret_cast<const float4*>(bb)[(b0 + i) * NG + g];
        sbox[i][g]  = g4;
        sarea[i][g] = __fmul_rn(g4.z - g4.x + 1.0f, g4.w - g4.y + 1.0f);
        sid[i][g]   = (float)ids[(b0 + i) * NG + g];
    }

    // Level of this block (blocks never span levels: 192/48/12/3/1).
    const int bx = blockIdx.x;
    int lvl = 0;
#pragma unroll
    for (int l = 1; l < NLVL; l++)
        if (bx >= L.boff[l]) lvl = l;

    const float* anch = sel_anchor(lvl, a0, a1, a2, a3, a4);
    const int nA    = L.aoff[lvl + 1] - L.aoff[lvl];
    const int local = (bx - L.boff[lvl]) * TPB + tid;   // one anchor per thread
    const bool act  = local < nA;

    // Anchor (loaded ONCE for all BPB batches).
    float4 av = make_float4(4e9f, 4e9f, 4e9f, 4e9f);    // sentinel: never overlaps
    if (act) av = reinterpret_cast<const float4*>(anch)[local];
    const float areaA = __fmul_rn(av.z - av.x + 1.0f, av.w - av.y + 1.0f);
    const unsigned lowb = 0xFFFFFFFFu - (unsigned)local;

    // Warp bbox via REDUX on biased coords (all coords > -2048 => biased > 0 =>
    // float bits order as uints). Inactive threads: min-cands = +INF, max-cands
    // biased to 0 => never win. Bias rounding << the ±2 margin.
    const float INF = __int_as_float(0x7F800000);
    float tx1 = act ? av.x : INF,      ty1 = act ? av.y : INF;
    float tx2 = act ? av.z : -2048.0f, ty2 = act ? av.w : -2048.0f;
    unsigned ux1 = __reduce_min_sync(0xFFFFFFFFu, __float_as_uint(tx1 + 2048.0f));
    unsigned uy1 = __reduce_min_sync(0xFFFFFFFFu, __float_as_uint(ty1 + 2048.0f));
    unsigned ux2 = __reduce_max_sync(0xFFFFFFFFu, __float_as_uint(tx2 + 2048.0f));
    unsigned uy2 = __reduce_max_sync(0xFFFFFFFFu, __float_as_uint(ty2 + 2048.0f));
    const float wx1 = (__uint_as_float(ux1) - 2048.0f) - 2.0f;
    const float wy1 = (__uint_as_float(uy1) - 2048.0f) - 2.0f;
    const float wx2 = (__uint_as_float(ux2) - 2048.0f) + 2.0f;
    const float wy2 = (__uint_as_float(uy2) - 2048.0f) + 2.0f;

    __syncthreads();

    const int Atot = L.aoff[NLVL];
    const int aglob = L.aoff[lvl] + local;
    float* reg_base = out + (size_t)NB * Atot;

    // ── Batch loop: all fixed costs above amortized over BPB batches ──
#pragma unroll 1
    for (int i = 0; i < BPB; ++i) {
        const int b = b0 + i;

        // Ballot survival mask: lane g tests GT g against the warp bbox.
        bool surv = false;
        if (lane < NG) {
            float4 gb = sbox[i][lane];
            surv = (gb.z >= wx1) && (gb.x <= wx2) && (gb.w >= wy1) && (gb.y <= wy2);
        }
        unsigned mask = __ballot_sync(0xFFFFFFFFu, surv);

        float best = 0.0f;   // zero-overlap rows => argmax g=0, matching jnp
        int   bestg = 0;
        const unsigned long long gbase = (unsigned long long)(b * NLVL + lvl) * NG;

        // Surviving GTs only, ascending g (preserves first-wins ties).
        while (mask) {
            const int g = __ffs(mask) - 1;
            mask &= mask - 1;

            float4 gb  = sbox[i][g];
            float iw = fminf(av.z, gb.z) - fmaxf(av.x, gb.x) + 1.0f;
            float ih = fminf(av.w, gb.w) - fmaxf(av.y, gb.y) + 1.0f;
            float pv = 0.0f;
            if (iw > 0.0f && ih > 0.0f) {
                float inter = __fmul_rn(iw, ih);
                float denom = __fsub_rn(__fadd_rn(areaA, sarea[i][g]), inter);
                float iou   = div_rn_fast(inter, denom);   // == IEEE rn div bits
                if (iou > best) { best = iou; bestg = g; } // strict > => first wins
                pv = iou;
            }
            // Warp reduction via REDUX: max iou bits, then min idx among ties.
            unsigned hv = __float_as_uint(pv);
            unsigned mh = __reduce_max_sync(0xFFFFFFFFu, hv);
            if (mh != 0u) {   // warp-uniform
                unsigned lo = (hv == mh) ? lowb : 0u;
                unsigned ml = __reduce_max_sync(0xFFFFFFFFu, lo);
                if (lane == 0)
                    atomicMax(&g_gtpack[gbase + g],
                              ((unsigned long long)mh << 32) | (unsigned long long)ml);
            }
        }

        // Per-anchor epilogue for this batch.
        if (act) {
            const bool pos    = best >= 0.5f;
            const bool ignore = best >= 0.4f;
            out[(size_t)b * Atot + aglob] =
                pos ? sid[i][bestg] : (ignore ? -1.0f : 0.0f);

            float4 r = make_float4(0.f, 0.f, 0.f, 0.f);
            if (pos) {
                float4 gb = sbox[i][bestg];
                float ew  = av.z - av.x + 1.0f;
                float eh  = av.w - av.y + 1.0f;
                float ecx = av.x + 0.5f * ew;
                float ecy = av.y + 0.5f * eh;
                float gw  = gb.z - gb.x + 1.0f;
                float gh  = gb.w - gb.y + 1.0f;
                float gcx = gb.x + 0.5f * gw;
                float gcy = gb.y + 0.5f * gh;
                r.x = div_rn_fast(gcx - ecx, ew);
                r.y = div_rn_fast(gcy - ecy, eh);
                r.z = logf(div_rn_fast(gw, ew));
                r.w = logf(div_rn_fast(gh, eh));
            }
            reinterpret_cast<float4*>(reg_base)[(size_t)b * Atot + aglob] = r;
        }
    }

    // ── Last-block-done: final block applies forced positives ──
    __syncthreads();
    if (tid == 0) {
        __threadfence();   // cumulative fence: orders the whole block's prior
                           // REDs/STGs (made visible via the barrier) at device scope
        int n = atomicAdd(&g_done, 1);
        s_last = (n == (int)(gridDim.x * gridDim.y) - 1);
    }
    __syncthreads();
    if (!s_last) return;
    __threadfence();       // acquire: see every block's atomics/stores

    for (int t = tid; t < NB * NG; t += TPB) {
        const int bb_i = t / NG, g = t % NG;

        // argmax over levels; strict >, ascending => first max wins
        // (bit-exact vs jnp.stack(...).argmax(axis=0)).
        float bestv = -1.0f;
        int bl = 0;
        unsigned long long bp = 0ull;
#pragma unroll
        for (int l = 0; l < NLVL; l++) {
            unsigned long long p = g_gtpack[(bb_i * NLVL + l) * NG + g];
            float v = __uint_as_float((unsigned)(p >> 32));
            if (v > bestv) { bestv = v; bl = l; bp = p; }
        }
        int loc = (int)(0xFFFFFFFFu - (unsigned)(bp & 0xFFFFFFFFull));
        int ag  = L.aoff[bl] + loc;

        const float* ap = sel_anchor(bl, a0, a1, a2, a3, a4) + (size_t)loc * 4;
        float ax1 = ap[0], ay1 = ap[1], ax2 = ap[2], ay2 = ap[3];
        float4 gb = reinterpret_cast<const float4*>(bb)[bb_i * NG + g];

        float ew  = ax2 - ax1 + 1.0f;
        float eh  = ay2 - ay1 + 1.0f;
        float ecx = ax1 + 0.5f * ew;
        float ecy = ay1 + 0.5f * eh;
        float gw  = gb.z - gb.x + 1.0f;
        float gh  = gb.w - gb.y + 1.0f;
        float gcx = gb.x + 0.5f * gw;
        float gcy = gb.y + 0.5f * gh;
        float4 r;
        r.x = div_rn_fast(gcx - ecx, ew);
        r.y = div_rn_fast(gcy - ecy, eh);
        r.z = logf(div_rn_fast(gw, ew));
        r.w = logf(div_rn_fast(gh, eh));

        s_ag[t]  = ag;
        s_lab[t] = (float)ids[bb_i * NG + g];
        s_reg[t] = r;
    }
    __syncthreads();

    if (tid < NB) {  // thread = batch; ascending g => deterministic last-wins
        for (int g = 0; g < NG; ++g) {
            int idx = tid * NG + g;
            int ag  = s_ag[idx];
            out[(size_t)tid * Atot + ag] = s_lab[idx];
            reinterpret_cast<float4*>(reg_base)[(size_t)tid * Atot + ag] = s_reg[idx];
        }
    }

    // Reset scratch for the next launch / graph replay.
    if (tid == 0) g_done = 0;
    for (int i = tid; i < NB * NLVL * NG; i += TPB)
        g_gtpack[i] = 0ull;
}

extern "C" void kernel_launch(void* const* d_in, const int* in_sizes, int n_in,
                              void* d_out, int out_size) {
    const float* bb  = (const float*)d_in[0];
    const int*   ids = (const int*)d_in[1];
    const float* A[NLVL];
    LvlInfo L;
    L.aoff[0] = 0;
    L.boff[0] = 0;
    for (int l = 0; l < NLVL; l++) {
        A[l] = (const float*)d_in[2 + l];
        int nA = in_sizes[2 + l] / 4;
        L.aoff[l + 1] = L.aoff[l] + nA;
        L.boff[l + 1] = L.boff[l] + (nA + TPB - 1) / TPB;
    }
    float* out = (float*)d_out;

    dim3 grid(L.boff[NLVL], NBG);
    main_kernel<<<grid, TPB>>>(bb, ids, A[0], A[1], A[2], A[3], A[4], out, L);
}

// round 14
// speedup vs baseline: 2.0728x; 2.0728x over previous
#include <cuda_runtime.h>
#include <cuda_bf16.h>

#define TPB   256
#define APT   2            // anchors per thread (ADJACENT pair: 2t, 2t+1)
#define NB    32           // batch
#define NG    20           // GT boxes per image
#define NLVL  5

struct LvlInfo {
    int aoff[NLVL + 1];
    int boff[NLVL + 1];
};

// Packed (iou_bits << 32) | (0xFFFFFFFF - local_anchor_idx) per (b,lvl,g).
// IoU >= 0 => float bits order as uints; inverted idx => atomicMax ties to the
// SMALLEST anchor index (jnp.argmax first-wins). Zero at load; last block
// re-zeroes after consuming, so graph replays start clean.
__device__ unsigned long long g_gtpack[NB * NLVL * NG];
__device__ int g_done;

// Correctly-rounded fp32 division, branch-free (Markstein fast path).
// Bit-identical to IEEE div.rn.f32 for the operands seen here.
__device__ __forceinline__ float div_rn_fast(float n, float d) {
    float r;
    asm("rcp.approx.ftz.f32 %0, %1;" : "=f"(r) : "f"(d));
    float e  = __fmaf_rn(-d, r, 1.0f);
    r        = __fmaf_rn(e, r, r);
    float q  = __fmul_rn(n, r);
    float e2 = __fmaf_rn(-d, q, n);
    return __fmaf_rn(e2, r, q);
}

__device__ __forceinline__ const float* sel_anchor(int l,
    const float* a0, const float* a1, const float* a2, const float* a3, const float* a4) {
    switch (l) {
        case 0: return a0;
        case 1: return a1;
        case 2: return a2;
        case 3: return a3;
        default: return a4;
    }
}

__global__ __launch_bounds__(TPB) void main_kernel(
    const float* __restrict__ bb,   // (B, G, 4)
    const int*   __restrict__ ids,  // (B, G)
    const float* __restrict__ a0, const float* __restrict__ a1,
    const float* __restrict__ a2, const float* __restrict__ a3,
    const float* __restrict__ a4,
    float* __restrict__ out, LvlInfo L)
{
    __shared__ float4 sbox[NG];
    __shared__ float  sarea[NG], sid[NG];
    __shared__ int    s_last;
    // Fixup staging (used only by the last block; ~15.4 KB).
    __shared__ int    s_ag[NB * NG];
    __shared__ float  s_lab[NB * NG];
    __shared__ __align__(16) float4 s_reg[NB * NG];

    const int b    = blockIdx.y;
    const int tid  = threadIdx.x;
    const int lane = tid & 31;

    if (tid < NG) {
        float4 g4 = reinterpret_cast<const float4*>(bb)[b * NG + tid];
        sbox[tid]  = g4;
        sarea[tid] = __fmul_rn(g4.z - g4.x + 1.0f, g4.w - g4.y + 1.0f);
        sid[tid]   = (float)ids[b * NG + tid];
    }

    // Level of this block (blocks never span levels: 96/24/6/2/1).
    const int bx = blockIdx.x;
    int lvl = 0;
#pragma unroll
    for (int l = 1; l < NLVL; l++)
        if (bx >= L.boff[l]) lvl = l;

    const float* anch = sel_anchor(lvl, a0, a1, a2, a3, a4);
    const int nA = L.aoff[lvl + 1] - L.aoff[lvl];
    // ADJACENT pair: thread owns anchors base+0, base+1 => warp owns 64
    // consecutive anchors => tight warp bbox for pruning. nA is even, so a
    // thread's pair is uniformly active.
    const int base = ((bx - L.boff[lvl]) * TPB + tid) * APT;
    const bool act = base < nA;

    float4   av[APT];
    float    areaA[APT];
    unsigned lowb[APT];
    float    best[APT];
    int      bestg[APT];

    const float INF = __int_as_float(0x7F800000);
    // Inactive threads: min-candidates = +INF (never win min); max-candidates
    // = -2048 (biased to 0, never win max).
    float tx1 = INF, ty1 = INF, tx2 = -2048.0f, ty2 = -2048.0f;

#pragma unroll
    for (int k = 0; k < APT; k++) {
        av[k] = make_float4(4e9f, 4e9f, 4e9f, 4e9f);   // sentinel: never overlaps
        if (act) av[k] = reinterpret_cast<const float4*>(anch)[base + k];
        areaA[k] = __fmul_rn(av[k].z - av[k].x + 1.0f, av[k].w - av[k].y + 1.0f);
        lowb[k]  = 0xFFFFFFFFu - (unsigned)(base + k);
        best[k]  = 0.0f;   // zero-overlap rows => argmax g=0, matching jnp
        bestg[k] = 0;
    }
    if (act) {
#pragma unroll
        for (int k = 0; k < APT; k++) {
            tx1 = fminf(tx1, av[k].x); ty1 = fminf(ty1, av[k].y);
            tx2 = fmaxf(tx2, av[k].z); ty2 = fmaxf(ty2, av[k].w);
        }
    }

    // Warp bbox via REDUX on biased coords (coords > -2048 => biased > 0 =>
    // float bits order as uints). Bias rounding << the ±2 margin below.
    unsigned ux1 = __reduce_min_sync(0xFFFFFFFFu, __float_as_uint(tx1 + 2048.0f));
    unsigned uy1 = __reduce_min_sync(0xFFFFFFFFu, __float_as_uint(ty1 + 2048.0f));
    unsigned ux2 = __reduce_max_sync(0xFFFFFFFFu, __float_as_uint(tx2 + 2048.0f));
    unsigned uy2 = __reduce_max_sync(0xFFFFFFFFu, __float_as_uint(ty2 + 2048.0f));
    // Conservative overlap bounds (margin 2 > the +1 IoU slack + bias rounding).
    const float wx1 = (__uint_as_float(ux1) - 2048.0f) - 2.0f;
    const float wy1 = (__uint_as_float(uy1) - 2048.0f) - 2.0f;
    const float wx2 = (__uint_as_float(ux2) - 2048.0f) + 2.0f;
    const float wy2 = (__uint_as_float(uy2) - 2048.0f) + 2.0f;

    __syncthreads();

    // Ballot survival mask: lane g tests GT g.
    unsigned mask;
    {
        bool surv = false;
        if (lane < NG) {
            float4 gb = sbox[lane];
            surv = (gb.z >= wx1) && (gb.x <= wx2) && (gb.w >= wy1) && (gb.y <= wy2);
        }
        mask = __ballot_sync(0xFFFFFFFFu, surv);
    }

    const unsigned long long gbase = (unsigned long long)(b * NLVL + lvl) * NG;

    // Iterate surviving GTs only, ascending g (preserves first-wins ties).
    while (mask) {
        const int g = __ffs(mask) - 1;
        mask &= mask - 1;

        float4 gb  = sbox[g];
        float  sag = sarea[g];
        float    pv  = 0.0f;
        unsigned plo = 0u;
#pragma unroll
        for (int k = 0; k < APT; k++) {
            float iw = fminf(av[k].z, gb.z) - fmaxf(av[k].x, gb.x) + 1.0f;
            float ih = fminf(av[k].w, gb.w) - fmaxf(av[k].y, gb.y) + 1.0f;
            if (iw > 0.0f && ih > 0.0f) {
                float inter = __fmul_rn(iw, ih);
                float denom = __fsub_rn(__fadd_rn(areaA[k], sag), inter);
                float iou   = div_rn_fast(inter, denom);   // == IEEE rn div bits
                if (iou > best[k]) { best[k] = iou; bestg[k] = g; }
                // strict >: tie keeps k=0 (smaller idx) — matches u64-max.
                if (iou > pv) { pv = iou; plo = lowb[k]; }
            }
        }
        // Warp max of iou bits via REDUX; tie-break by ballot: lanes are in
        // ascending anchor order => plo strictly descends across lanes => the
        // LOWEST lane with hv==mh holds the max plo (smallest anchor idx).
        unsigned hv = __float_as_uint(pv);
        unsigned mh = __reduce_max_sync(0xFFFFFFFFu, hv);
        if (mh != 0u) {   // warp-uniform
            unsigned winners = __ballot_sync(0xFFFFFFFFu, hv == mh);
            if (lane == __ffs(winners) - 1)
                atomicMax(&g_gtpack[gbase + g],
                          ((unsigned long long)mh << 32) | (unsigned long long)plo);
        }
    }

    // Per-anchor outputs. Labels for the pair merge into one 8B store.
    const int Atot = L.aoff[NLVL];
    float* reg_base = out + (size_t)NB * Atot;
    if (act) {
        const int aglob0 = L.aoff[lvl] + base;
        float labv[APT];
#pragma unroll
        for (int k = 0; k < APT; k++) {
            const bool pos    = best[k] >= 0.5f;
            const bool ignore = best[k] >= 0.4f;
            labv[k] = pos ? sid[bestg[k]] : (ignore ? -1.0f : 0.0f);

            float4 r = make_float4(0.f, 0.f, 0.f, 0.f);
            if (pos) {
                float4 gb = sbox[bestg[k]];
                float ew  = av[k].z - av[k].x + 1.0f;
                float eh  = av[k].w - av[k].y + 1.0f;
                float ecx = av[k].x + 0.5f * ew;
                float ecy = av[k].y + 0.5f * eh;
                float gw  = gb.z - gb.x + 1.0f;
                float gh  = gb.w - gb.y + 1.0f;
                float gcx = gb.x + 0.5f * gw;
                float gcy = gb.y + 0.5f * gh;
                r.x = div_rn_fast(gcx - ecx, ew);
                r.y = div_rn_fast(gcy - ecy, eh);
                r.z = logf(div_rn_fast(gw, ew));
                r.w = logf(div_rn_fast(gh, eh));
            }
            reinterpret_cast<float4*>(reg_base)[(size_t)b * Atot + aglob0 + k] = r;
        }
        // (b*Atot + aglob0) is even => aligned float2 store.
        reinterpret_cast<float2*>(out)[((size_t)b * Atot + aglob0) >> 1] =
            make_float2(labv[0], labv[1]);
    }

    // ── Last-block-done: final block applies forced positives ──
    __syncthreads();
    if (tid == 0) {
        __threadfence();   // cumulative: orders the block's REDs/STGs (hb via
                           // the barrier) at device scope before the ticket
        int n = atomicAdd(&g_done, 1);
        s_last = (n == (int)(gridDim.x * gridDim.y) - 1);
    }
    __syncthreads();
    if (!s_last) return;
    __threadfence();       // acquire: see every block's atomics/stores

    for (int t = tid; t < NB * NG; t += TPB) {
        const int bb_i = t / NG, g = t % NG;

        // argmax over levels; strict >, ascending => first max wins
        // (bit-exact vs jnp.stack(...).argmax(axis=0)).
        float bestv = -1.0f;
        int bl = 0;
        unsigned long long bp = 0ull;
#pragma unroll
        for (int l = 0; l < NLVL; l++) {
            unsigned long long p = g_gtpack[(bb_i * NLVL + l) * NG + g];
            float v = __uint_as_float((unsigned)(p >> 32));
            if (v > bestv) { bestv = v; bl = l; bp = p; }
        }
        int local = (int)(0xFFFFFFFFu - (unsigned)(bp & 0xFFFFFFFFull));
        int aglob = L.aoff[bl] + local;

        const float* ap = sel_anchor(bl, a0, a1, a2, a3, a4) + (size_t)local * 4;
        float ax1 = ap[0], ay1 = ap[1], ax2 = ap[2], ay2 = ap[3];
        float4 gb = reinterpret_cast<const float4*>(bb)[bb_i * NG + g];

        float ew  = ax2 - ax1 + 1.0f;
        float eh  = ay2 - ay1 + 1.0f;
        float ecx = ax1 + 0.5f * ew;
        float ecy = ay1 + 0.5f * eh;
        float gw  = gb.z - gb.x + 1.0f;
        float gh  = gb.w - gb.y + 1.0f;
        float gcx = gb.x + 0.5f * gw;
        float gcy = gb.y + 0.5f * gh;
        float4 r;
        r.x = div_rn_fast(gcx - ecx, ew);
        r.y = div_rn_fast(gcy - ecy, eh);
        r.z = logf(div_rn_fast(gw, ew));
        r.w = logf(div_rn_fast(gh, eh));

        s_ag[t]  = aglob;
        s_lab[t] = (float)ids[bb_i * NG + g];
        s_reg[t] = r;
    }
    __syncthreads();

    if (tid < NB) {  // thread = batch; ascending g => deterministic last-wins
        for (int g = 0; g < NG; ++g) {
            int i = tid * NG + g;
            int aglob = s_ag[i];
            out[(size_t)tid * Atot + aglob] = s_lab[i];
            reinterpret_cast<float4*>(reg_base)[(size_t)tid * Atot + aglob] = s_reg[i];
        }
    }

    // Reset scratch for the next launch / graph replay.
    if (tid == 0) g_done = 0;
    for (int i = tid; i < NB * NLVL * NG; i += TPB)
        g_gtpack[i] = 0ull;
}

extern "C" void kernel_launch(void* const* d_in, const int* in_sizes, int n_in,
                              void* d_out, int out_size) {
    const float* bb  = (const float*)d_in[0];
    const int*   ids = (const int*)d_in[1];
    const float* A[NLVL];
    LvlInfo L;
    L.aoff[0] = 0;
    L.boff[0] = 0;
    for (int l = 0; l < NLVL; l++) {
        A[l] = (const float*)d_in[2 + l];
        int nA = in_sizes[2 + l] / 4;
        L.aoff[l + 1] = L.aoff[l] + nA;
        L.boff[l + 1] = L.boff[l] + (nA + TPB * APT - 1) / (TPB * APT);
    }
    float* out = (float*)d_out;

    dim3 grid(L.boff[NLVL], NB);
    main_kernel<<<grid, TPB>>>(bb, ids, A[0], A[1], A[2], A[3], A[4], out, L);
}